// round 17
// baseline (speedup 1.0000x reference)
#include <cuda_runtime.h>

// DynamicGraphModule_15144054686343 — FINAL (converged; held unchanged since R8,
// re-confirmed through R16. 14 valid benches all in {6.624, 6.656, 6.880} us,
// rel_err exactly 0 on every run.)
//
// Reference math reduces analytically:
//   scores[i,j] = row_term[i] + col_term[j] + b   (rank-1 + const)
//   adj = where(corr > 1.5, corr, 0)   -> elements in {0} U (1.5, inf)
//   adj = where(adj < -1.5, adj, 0)    -> identically ZERO (thresholds are
//                                         mutually exclusive)
//   out = adj @ (e @ W_gcn) + b_gcn    == broadcast(b_gcn) exactly
//                                         (fp32 0*x accumulates to 0.0 bitwise)
//
// Kernel: broadcast b_gcn [512] into out [1, 4096, 512] (8 MB fp32 stores).
//
// Convergence evidence (R0-R16, 14 valid benches, 7 variants): occupancy
// 17-102%, 1-8 stores/thread, STG.128 / STG.256 / TMA-bulk, and load-
// scheduling tweaks all land in bench {6.624, 6.656, 6.880} us; identical
// source re-runs span the same set -> the spread is run-to-run noise. No pipe
// exceeds 17.5% in any profile (DRAM 0%, L2 ~15%, issue <= 17%). Duration =
// fixed floor: ~0.7 us of L2-resident write traffic + launch/ramp/drain +
// graph-replay constant. One kernel, one wave, depth-1 chain, minimal
// traffic, bitwise-exact output: no structural headroom remains.

static constexpr int D_OUT_VEC4 = 128;          // 512 floats per row = 128 float4
static constexpr int TOTAL_VEC4 = 4096 * 128;   // 524288 float4 = 8 MB

__global__ void __launch_bounds__(256)
broadcast_bias_kernel(const float4* __restrict__ bias4,
                      float4* __restrict__ out4)
{
    // Load address depends on threadIdx only (blockDim.x = 256, multiple of
    // 128), so the LDG issues ahead of the store-address IMAD chain; the bias
    // line is L2-broadcast across all SMs.
    const float4 b = bias4[threadIdx.x & (D_OUT_VEC4 - 1)];

    const int idx = blockIdx.x * blockDim.x + threadIdx.x;   // 0..524287
    out4[idx] = b;                                           // coalesced STG.128
}

extern "C" void kernel_launch(void* const* d_in, const int* in_sizes, int n_in,
                              void* d_out, int out_size)
{
    // metadata order:
    // 0 spans_embeddings, 1 W_c1, 2 b_c1, 3 W_c2, 4 b_c2,
    // 5 W_link, 6 b_link, 7 W_gcn, 8 b_gcn
    const float4* bias4 = (const float4*)d_in[8];
    float4* out4 = (float4*)d_out;
    (void)in_sizes; (void)n_in; (void)out_size;   // out_size = 4096*512 exactly

    broadcast_bias_kernel<<<TOTAL_VEC4 / 256, 256>>>(bias4, out4);
}